// round 10
// baseline (speedup 1.0000x reference)
#include <cuda_runtime.h>

#define NN 50000
#define EE 800000
#define FF 100
#define HH 64
#define CC 40
#define W1CAT 192   // [A=x@W1[1] | B=x@W1[2] | C0=x@(W1[0]-W1[2])]
#define W2CAT 120   // [A2 | B2 | C2]

// ---------------- scratch (device globals; no allocations allowed) ----------
__device__ int   g_is64;
__device__ int   g_deg[NN];
__device__ int   g_rowptr[NN + 1];
__device__ int   g_cursor[NN];
__device__ int   g_col[EE];
__device__ float g_w[EE];
__device__ float g_dinv[NN];
__device__ float g_Wcat1[FF * W1CAT];
__device__ float g_Wcat2[HH * W2CAT];
__device__ float g_XW[NN * W1CAT];
__device__ float g_U[NN * HH];
__device__ float g_h[NN * HH];
__device__ float g_HW[NN * W2CAT];
__device__ float g_U2[NN * CC];

// ---------------- dtype detection (PARALLEL, was serial bottleneck) ----------
// 1024 threads each sample ONE int64 slot (all loads in flight simultaneously).
// True int64 edge data lies in [0, NN); int32 data read as int64 = a + b*2^32.
__global__ void k_detect_dtype(const long long* __restrict__ ei) {
    __shared__ int s_ok;
    int tid = threadIdx.x;            // 1024 threads
    if (tid == 0) s_ok = 1;
    __syncthreads();
    long long v = ei[tid * 781];      // max index 1023*781 = 798,963 < EE
    if (v < 0 || v >= NN) s_ok = 0;   // benign race: only 0 is written
    __syncthreads();
    if (tid == 0) g_is64 = s_ok;
}

// ---------------- init: zero degrees + weight concat (merged) ----------------
// W1: (3,100,64) row-major; W2: (3,64,40)
__global__ void k_init(const float* __restrict__ W1, const float* __restrict__ W2) {
    int i = blockIdx.x * blockDim.x + threadIdx.x;
    if (i < NN) g_deg[i] = 0;
    if (i < FF * W1CAT) {
        int f = i / W1CAT, j = i % W1CAT;
        float v;
        if (j < 64)       v = W1[6400 + f * 64 + j];
        else if (j < 128) v = W1[12800 + f * 64 + (j - 64)];
        else              v = W1[f * 64 + (j - 128)] - W1[12800 + f * 64 + (j - 128)];
        g_Wcat1[i] = v;
    }
    if (i < HH * W2CAT) {
        int f = i / W2CAT, j = i % W2CAT;
        float v;
        if (j < 40)      v = W2[2560 + f * 40 + j];
        else if (j < 80) v = W2[5120 + f * 40 + (j - 40)];
        else             v = W2[f * 40 + (j - 80)] - W2[5120 + f * 40 + (j - 80)];
        g_Wcat2[i] = v;
    }
}

// ---------------- graph setup ------------------------------------------------
__global__ void k_count_deg(const long long* __restrict__ ei64,
                            const int* __restrict__ ei32) {
    int e = blockIdx.x * blockDim.x + threadIdx.x;
    if (e < EE) {
        long long r = g_is64 ? ei64[e] : (long long)ei32[e];
        if (r >= 0 && r < NN) atomicAdd(&g_deg[(int)r], 1);
    }
}

// single-block scan of g_deg -> g_rowptr/g_cursor, plus dinv (merged)
__global__ void k_scan_dinv() {
    __shared__ int warpsums[8];
    const int n = NN;
    int tid = threadIdx.x;                       // 256 threads
    const int chunk = (NN + 255) / 256;
    int start = tid * chunk;
    int end = min(start + chunk, n);

    int local = 0;
    for (int i = start; i < end; i++) local += g_deg[i];

    int lane = tid & 31, wid = tid >> 5;
    int v = local;
    #pragma unroll
    for (int o = 1; o < 32; o <<= 1) {
        int t = __shfl_up_sync(0xffffffffu, v, o);
        if (lane >= o) v += t;
    }
    if (lane == 31) warpsums[wid] = v;
    __syncthreads();
    if (tid == 0) {
        int run = 0;
        #pragma unroll
        for (int i = 0; i < 8; i++) { int t = warpsums[i]; warpsums[i] = run; run += t; }
    }
    __syncthreads();
    int excl = v - local + warpsums[wid];

    int run = excl;
    for (int i = start; i < end; i++) {
        int d = g_deg[i];
        g_rowptr[i] = run;
        g_cursor[i] = run;
        g_dinv[i] = (d > 0) ? rsqrtf((float)d) : 0.0f;
        run += d;
    }
    if (start < n && end == n) g_rowptr[n] = run;
}

__global__ void k_fill_csr(const long long* __restrict__ ei64,
                           const int* __restrict__ ei32) {
    int e = blockIdx.x * blockDim.x + threadIdx.x;
    if (e < EE) {
        long long rl, cl;
        if (g_is64) { rl = ei64[e]; cl = ei64[EE + e]; }
        else        { rl = (long long)ei32[e]; cl = (long long)ei32[EE + e]; }
        if (rl < 0 || rl >= NN || cl < 0 || cl >= NN) return;
        int r = (int)rl, c = (int)cl;
        int pos = atomicAdd(&g_cursor[r], 1);
        if (pos >= 0 && pos < EE) {
            g_col[pos] = c;
            g_w[pos] = -(g_dinv[r] * g_dinv[c]);
        }
    }
}

// ---------------- SIMT fp32 GEMM: 64x64 block tile, 4x4 per thread ----------
template <int Kd, int Nc>
__device__ __forceinline__ void gemm_core(
    const float* __restrict__ A, const float* __restrict__ B, float* __restrict__ C)
{
    __shared__ __align__(16) float As[16][68];
    __shared__ __align__(16) float Bs[16][68];
    const int M = NN;
    int tid = threadIdx.x;
    int tx = tid % 16, ty = tid / 16;
    int m0 = blockIdx.x * 64, n0 = blockIdx.y * 64;

    float acc[4][4];
    #pragma unroll
    for (int i = 0; i < 4; i++)
        #pragma unroll
        for (int j = 0; j < 4; j++) acc[i][j] = 0.0f;

    for (int k0 = 0; k0 < Kd; k0 += 16) {
        #pragma unroll
        for (int i = tid; i < 64 * 16; i += 256) {
            int k = i % 16, m = i / 16;
            int gm = m0 + m, gk = k0 + k;
            As[k][m] = (gm < M && gk < Kd) ? A[gm * Kd + gk] : 0.0f;
        }
        #pragma unroll
        for (int i = tid; i < 16 * 64; i += 256) {
            int n = i % 64, k = i / 64;
            int gk = k0 + k, gn = n0 + n;
            Bs[k][n] = (gk < Kd && gn < Nc) ? B[gk * Nc + gn] : 0.0f;
        }
        __syncthreads();
        #pragma unroll
        for (int k = 0; k < 16; k++) {
            float4 av = *(const float4*)&As[k][ty * 4];
            float4 bv = *(const float4*)&Bs[k][tx * 4];
            float a[4] = {av.x, av.y, av.z, av.w};
            float b[4] = {bv.x, bv.y, bv.z, bv.w};
            #pragma unroll
            for (int i = 0; i < 4; i++)
                #pragma unroll
                for (int j = 0; j < 4; j++) acc[i][j] += a[i] * b[j];
        }
        __syncthreads();
    }
    #pragma unroll
    for (int i = 0; i < 4; i++) {
        int gm = m0 + ty * 4 + i;
        if (gm >= M) continue;
        #pragma unroll
        for (int j = 0; j < 4; j++) {
            int gn = n0 + tx * 4 + j;
            if (gn < Nc) C[gm * Nc + gn] = acc[i][j];
        }
    }
}

__global__ __launch_bounds__(256) void k_gemm1(const float* __restrict__ x) {
    gemm_core<FF, W1CAT>(x, g_Wcat1, g_XW);
}

__global__ __launch_bounds__(256) void k_gemm2() {
    gemm_core<HH, W2CAT>(g_h, g_Wcat2, g_HW);
}

// ---------------- SpMV kernels (warp-per-row CSR gather) ---------------------
__global__ void k_spmv_U() {
    int w = (blockIdx.x * blockDim.x + threadIdx.x) >> 5;
    int lane = threadIdx.x & 31;
    if (w >= NN) return;
    int s = g_rowptr[w], e = g_rowptr[w + 1];
    float a0 = 0.f, a1 = 0.f;
    for (int t = s; t < e; t++) {
        int c = g_col[t];
        float wt = g_w[t];
        const float* p = &g_XW[c * W1CAT + 64];
        a0 += wt * p[lane];
        a1 += wt * p[32 + lane];
    }
    g_U[w * 64 + lane]      = g_XW[w * W1CAT + lane]      + 2.0f * a0;
    g_U[w * 64 + 32 + lane] = g_XW[w * W1CAT + 32 + lane] + 2.0f * a1;
}

__global__ void k_spmv_h(const float* __restrict__ b1) {
    int w = (blockIdx.x * blockDim.x + threadIdx.x) >> 5;
    int lane = threadIdx.x & 31;
    if (w >= NN) return;
    int s = g_rowptr[w], e = g_rowptr[w + 1];
    float a0 = 0.f, a1 = 0.f;
    for (int t = s; t < e; t++) {
        int c = g_col[t];
        float wt = g_w[t];
        const float* p = &g_U[c * 64];
        a0 += wt * p[lane];
        a1 += wt * p[32 + lane];
    }
    float v0 = g_XW[w * W1CAT + 128 + lane] + a0 + b1[lane];
    float v1 = g_XW[w * W1CAT + 160 + lane] + a1 + b1[32 + lane];
    g_h[w * 64 + lane]      = fmaxf(v0, 0.0f);
    g_h[w * 64 + 32 + lane] = fmaxf(v1, 0.0f);
}

__global__ void k_spmv_U2() {
    int w = (blockIdx.x * blockDim.x + threadIdx.x) >> 5;
    int lane = threadIdx.x & 31;
    if (w >= NN) return;
    int s = g_rowptr[w], e = g_rowptr[w + 1];
    float a0 = 0.f, a1 = 0.f;
    for (int t = s; t < e; t++) {
        int c = g_col[t];
        float wt = g_w[t];
        a0 += wt * g_HW[c * W2CAT + 40 + lane];
        a1 += wt * g_HW[c * W2CAT + 72 + lane];  // cols 72..103 in-bounds; only lane<8 used
    }
    g_U2[w * CC + lane] = g_HW[w * W2CAT + lane] + 2.0f * a0;
    if (lane < 8)
        g_U2[w * CC + 32 + lane] = g_HW[w * W2CAT + 32 + lane] + 2.0f * a1;
}

__global__ void k_final(const float* __restrict__ b2, float* __restrict__ out) {
    int w = (blockIdx.x * blockDim.x + threadIdx.x) >> 5;
    int lane = threadIdx.x & 31;
    if (w >= NN) return;
    int s = g_rowptr[w], e = g_rowptr[w + 1];
    float a0 = 0.f, a1 = 0.f;
    for (int t = s; t < e; t++) {
        int c = g_col[t];
        float wt = g_w[t];
        a0 += wt * g_U2[c * CC + lane];
        if (lane < 8) a1 += wt * g_U2[c * CC + 32 + lane];
    }
    float z0 = g_HW[w * W2CAT + 80 + lane] + a0 + b2[lane];
    float z1 = (lane < 8) ? (g_HW[w * W2CAT + 112 + lane] + a1 + b2[32 + lane])
                          : __int_as_float(0xff800000);
    float m = fmaxf(z0, z1);
    #pragma unroll
    for (int o = 16; o > 0; o >>= 1) m = fmaxf(m, __shfl_xor_sync(0xffffffffu, m, o));
    float ssum = expf(z0 - m) + ((lane < 8) ? expf(z1 - m) : 0.0f);
    #pragma unroll
    for (int o = 16; o > 0; o >>= 1) ssum += __shfl_xor_sync(0xffffffffu, ssum, o);
    float l = logf(ssum);
    out[w * CC + lane] = z0 - m - l;
    if (lane < 8) out[w * CC + 32 + lane] = z1 - m - l;
}

// ---------------- launch -----------------------------------------------------
extern "C" void kernel_launch(void* const* d_in, const int* in_sizes, int n_in,
                              void* d_out, int out_size) {
    // Resolve inputs BY ELEMENT COUNT (all six distinct):
    // x=5,000,000  ei=1,600,000  W1=19,200  b1=64  W2=7,680  b2=40
    const float* x  = nullptr;
    const void*  ei = nullptr;
    const float* W1 = nullptr;
    const float* b1 = nullptr;
    const float* W2 = nullptr;
    const float* b2 = nullptr;
    for (int i = 0; i < n_in; i++) {
        switch (in_sizes[i]) {
            case NN * FF:     x  = (const float*)d_in[i]; break;
            case 2 * EE:      ei = d_in[i];               break;
            case 3 * FF * HH: W1 = (const float*)d_in[i]; break;
            case HH:          b1 = (const float*)d_in[i]; break;
            case 3 * HH * CC: W2 = (const float*)d_in[i]; break;
            case CC:          b2 = (const float*)d_in[i]; break;
            default: break;
        }
    }
    const long long* ei64 = (const long long*)ei;
    const int*       ei32 = (const int*)ei;
    float* out = (float*)d_out;

    const int TB = 256;
    int nodeBlocks = (NN + TB - 1) / TB;
    int edgeBlocks = (EE + TB - 1) / TB;
    int warpRowBlocks = (NN * 32 + TB - 1) / TB;

    k_detect_dtype<<<1, 1024>>>(ei64);            // parallel: ~2us (was serial ~200+us)
    k_init<<<nodeBlocks, TB>>>(W1, W2);           // zero deg + weight concat
    k_count_deg<<<edgeBlocks, TB>>>(ei64, ei32);
    k_scan_dinv<<<1, 256>>>();                    // rowptr + cursor + dinv
    k_fill_csr<<<edgeBlocks, TB>>>(ei64, ei32);

    {   // launch #6 — profiled by ncu (-s 5 -c 1)
        dim3 grid((NN + 63) / 64, (W1CAT + 63) / 64);
        k_gemm1<<<grid, 256>>>(x);
    }
    k_spmv_U<<<warpRowBlocks, TB>>>();
    k_spmv_h<<<warpRowBlocks, TB>>>(b1);

    {
        dim3 grid((NN + 63) / 64, (W2CAT + 63) / 64);
        k_gemm2<<<grid, 256>>>();
    }
    k_spmv_U2<<<warpRowBlocks, TB>>>();
    k_final<<<warpRowBlocks, TB>>>(b2, out);
}

// round 13
// speedup vs baseline: 1.3535x; 1.3535x over previous
#include <cuda_runtime.h>

#define NN 50000
#define EE 800000
#define FF 100
#define HH 64
#define CC 40
#define W1CAT 192   // [A=x@W1[1] | B=x@W1[2] | C0=x@(W1[0]-W1[2])]
#define W2CAT 120   // [A2 | B2 | C2]
#define SCAN_BLOCKS ((NN + 255) / 256)   // 196

// ---------------- scratch (device globals; no allocations allowed) ----------
__device__ int   g_is64;
__device__ int   g_deg[NN];
__device__ int   g_rowptr[NN + 1];
__device__ int   g_cursor[NN];
__device__ int   g_bsum[SCAN_BLOCKS];
__device__ int   g_col[EE];
__device__ float g_w[EE];
__device__ float g_dinv[NN];
__device__ float g_Wcat1[FF * W1CAT];
__device__ float g_Wcat2[HH * W2CAT];
__device__ float g_XW[NN * W1CAT];
__device__ float g_U[NN * HH];
__device__ float g_h[NN * HH];
__device__ float g_HW[NN * W2CAT];
__device__ float g_U2[NN * CC];

// ---------------- dtype detection (parallel) ---------------------------------
__global__ void k_detect_dtype(const long long* __restrict__ ei) {
    __shared__ int s_ok;
    int tid = threadIdx.x;            // 1024 threads
    if (tid == 0) s_ok = 1;
    __syncthreads();
    long long v = ei[tid * 781];      // max index 1023*781 = 798,963 < EE
    if (v < 0 || v >= NN) s_ok = 0;   // benign race: only 0 is written
    __syncthreads();
    if (tid == 0) g_is64 = s_ok;
}

// ---------------- init: zero degrees + weight concat (merged) ----------------
__global__ void k_init(const float* __restrict__ W1, const float* __restrict__ W2) {
    int i = blockIdx.x * blockDim.x + threadIdx.x;
    if (i < NN) g_deg[i] = 0;
    if (i < FF * W1CAT) {
        int f = i / W1CAT, j = i % W1CAT;
        float v;
        if (j < 64)       v = W1[6400 + f * 64 + j];
        else if (j < 128) v = W1[12800 + f * 64 + (j - 64)];
        else              v = W1[f * 64 + (j - 128)] - W1[12800 + f * 64 + (j - 128)];
        g_Wcat1[i] = v;
    }
    if (i < HH * W2CAT) {
        int f = i / W2CAT, j = i % W2CAT;
        float v;
        if (j < 40)      v = W2[2560 + f * 40 + j];
        else if (j < 80) v = W2[5120 + f * 40 + (j - 40)];
        else             v = W2[f * 40 + (j - 80)] - W2[5120 + f * 40 + (j - 80)];
        g_Wcat2[i] = v;
    }
}

// ---------------- graph setup ------------------------------------------------
__global__ void k_count_deg(const long long* __restrict__ ei64,
                            const int* __restrict__ ei32) {
    int e = blockIdx.x * blockDim.x + threadIdx.x;
    if (e < EE) {
        long long r = g_is64 ? ei64[e] : (long long)ei32[e];
        if (r >= 0 && r < NN) atomicAdd(&g_deg[(int)r], 1);
    }
}

// -------- 3-phase multi-block exclusive scan (was 103us single-block) --------
// Phase 1: block-local exclusive scan; local excl -> g_rowptr, block sum -> g_bsum
__global__ void k_scan1() {
    __shared__ int warpsums[8];
    int tid = threadIdx.x;
    int i = blockIdx.x * 256 + tid;
    int d = (i < NN) ? g_deg[i] : 0;

    int lane = tid & 31, wid = tid >> 5;
    int v = d;
    #pragma unroll
    for (int o = 1; o < 32; o <<= 1) {
        int t = __shfl_up_sync(0xffffffffu, v, o);
        if (lane >= o) v += t;
    }
    if (lane == 31) warpsums[wid] = v;
    __syncthreads();
    if (tid == 0) {
        int run = 0;
        #pragma unroll
        for (int k = 0; k < 8; k++) { int t = warpsums[k]; warpsums[k] = run; run += t; }
    }
    __syncthreads();
    int excl = v - d + warpsums[wid];
    if (i < NN) g_rowptr[i] = excl;                 // block-local offset (fixed in phase 3)
    if (tid == 255) g_bsum[blockIdx.x] = excl + d;  // block total
}

// Phase 2: single-block exclusive scan of the 196 block sums
__global__ void k_scan2() {
    __shared__ int warpsums[8];
    int tid = threadIdx.x;   // 256 threads
    int v0 = (tid < SCAN_BLOCKS) ? g_bsum[tid] : 0;

    int lane = tid & 31, wid = tid >> 5;
    int v = v0;
    #pragma unroll
    for (int o = 1; o < 32; o <<= 1) {
        int t = __shfl_up_sync(0xffffffffu, v, o);
        if (lane >= o) v += t;
    }
    if (lane == 31) warpsums[wid] = v;
    __syncthreads();
    if (tid == 0) {
        int run = 0;
        #pragma unroll
        for (int k = 0; k < 8; k++) { int t = warpsums[k]; warpsums[k] = run; run += t; }
    }
    __syncthreads();
    if (tid < SCAN_BLOCKS) g_bsum[tid] = v - v0 + warpsums[wid];
}

// Phase 3: add block offsets; emit rowptr/cursor/dinv (+ rowptr[NN])
__global__ void k_scan3() {
    int i = blockIdx.x * 256 + threadIdx.x;
    if (i < NN) {
        int r = g_rowptr[i] + g_bsum[blockIdx.x];
        g_rowptr[i] = r;
        g_cursor[i] = r;
        int d = g_deg[i];
        g_dinv[i] = (d > 0) ? rsqrtf((float)d) : 0.0f;
        if (i == NN - 1) g_rowptr[NN] = r + d;
    }
}

__global__ void k_fill_csr(const long long* __restrict__ ei64,
                           const int* __restrict__ ei32) {
    int e = blockIdx.x * blockDim.x + threadIdx.x;
    if (e < EE) {
        long long rl, cl;
        if (g_is64) { rl = ei64[e]; cl = ei64[EE + e]; }
        else        { rl = (long long)ei32[e]; cl = (long long)ei32[EE + e]; }
        if (rl < 0 || rl >= NN || cl < 0 || cl >= NN) return;
        int r = (int)rl, c = (int)cl;
        int pos = atomicAdd(&g_cursor[r], 1);
        if (pos >= 0 && pos < EE) {
            g_col[pos] = c;
            g_w[pos] = -(g_dinv[r] * g_dinv[c]);
        }
    }
}

// ---------------- SIMT fp32 GEMM: 64x64 block tile, 4x4 per thread ----------
template <int Kd, int Nc>
__device__ __forceinline__ void gemm_core(
    const float* __restrict__ A, const float* __restrict__ B, float* __restrict__ C)
{
    __shared__ __align__(16) float As[16][68];
    __shared__ __align__(16) float Bs[16][68];
    const int M = NN;
    int tid = threadIdx.x;
    int tx = tid % 16, ty = tid / 16;
    int m0 = blockIdx.x * 64, n0 = blockIdx.y * 64;

    float acc[4][4];
    #pragma unroll
    for (int i = 0; i < 4; i++)
        #pragma unroll
        for (int j = 0; j < 4; j++) acc[i][j] = 0.0f;

    for (int k0 = 0; k0 < Kd; k0 += 16) {
        #pragma unroll
        for (int i = tid; i < 64 * 16; i += 256) {
            int k = i % 16, m = i / 16;
            int gm = m0 + m, gk = k0 + k;
            As[k][m] = (gm < M && gk < Kd) ? A[gm * Kd + gk] : 0.0f;
        }
        #pragma unroll
        for (int i = tid; i < 16 * 64; i += 256) {
            int n = i % 64, k = i / 64;
            int gk = k0 + k, gn = n0 + n;
            Bs[k][n] = (gk < Kd && gn < Nc) ? B[gk * Nc + gn] : 0.0f;
        }
        __syncthreads();
        #pragma unroll
        for (int k = 0; k < 16; k++) {
            float4 av = *(const float4*)&As[k][ty * 4];
            float4 bv = *(const float4*)&Bs[k][tx * 4];
            float a[4] = {av.x, av.y, av.z, av.w};
            float b[4] = {bv.x, bv.y, bv.z, bv.w};
            #pragma unroll
            for (int i = 0; i < 4; i++)
                #pragma unroll
                for (int j = 0; j < 4; j++) acc[i][j] += a[i] * b[j];
        }
        __syncthreads();
    }
    #pragma unroll
    for (int i = 0; i < 4; i++) {
        int gm = m0 + ty * 4 + i;
        if (gm >= M) continue;
        #pragma unroll
        for (int j = 0; j < 4; j++) {
            int gn = n0 + tx * 4 + j;
            if (gn < Nc) C[gm * Nc + gn] = acc[i][j];
        }
    }
}

__global__ __launch_bounds__(256) void k_gemm1(const float* __restrict__ x) {
    gemm_core<FF, W1CAT>(x, g_Wcat1, g_XW);
}

__global__ __launch_bounds__(256) void k_gemm2() {
    gemm_core<HH, W2CAT>(g_h, g_Wcat2, g_HW);
}

// ---------------- SpMV kernels (warp-per-row CSR gather) ---------------------
__global__ void k_spmv_U() {
    int w = (blockIdx.x * blockDim.x + threadIdx.x) >> 5;
    int lane = threadIdx.x & 31;
    if (w >= NN) return;
    int s = g_rowptr[w], e = g_rowptr[w + 1];
    float a0 = 0.f, a1 = 0.f;
    for (int t = s; t < e; t++) {
        int c = g_col[t];
        float wt = g_w[t];
        const float* p = &g_XW[c * W1CAT + 64];
        a0 += wt * p[lane];
        a1 += wt * p[32 + lane];
    }
    g_U[w * 64 + lane]      = g_XW[w * W1CAT + lane]      + 2.0f * a0;
    g_U[w * 64 + 32 + lane] = g_XW[w * W1CAT + 32 + lane] + 2.0f * a1;
}

__global__ void k_spmv_h(const float* __restrict__ b1) {
    int w = (blockIdx.x * blockDim.x + threadIdx.x) >> 5;
    int lane = threadIdx.x & 31;
    if (w >= NN) return;
    int s = g_rowptr[w], e = g_rowptr[w + 1];
    float a0 = 0.f, a1 = 0.f;
    for (int t = s; t < e; t++) {
        int c = g_col[t];
        float wt = g_w[t];
        const float* p = &g_U[c * 64];
        a0 += wt * p[lane];
        a1 += wt * p[32 + lane];
    }
    float v0 = g_XW[w * W1CAT + 128 + lane] + a0 + b1[lane];
    float v1 = g_XW[w * W1CAT + 160 + lane] + a1 + b1[32 + lane];
    g_h[w * 64 + lane]      = fmaxf(v0, 0.0f);
    g_h[w * 64 + 32 + lane] = fmaxf(v1, 0.0f);
}

__global__ void k_spmv_U2() {
    int w = (blockIdx.x * blockDim.x + threadIdx.x) >> 5;
    int lane = threadIdx.x & 31;
    if (w >= NN) return;
    int s = g_rowptr[w], e = g_rowptr[w + 1];
    float a0 = 0.f, a1 = 0.f;
    for (int t = s; t < e; t++) {
        int c = g_col[t];
        float wt = g_w[t];
        a0 += wt * g_HW[c * W2CAT + 40 + lane];
        a1 += wt * g_HW[c * W2CAT + 72 + lane];  // cols 72..103 in-bounds; only lane<8 used
    }
    g_U2[w * CC + lane] = g_HW[w * W2CAT + lane] + 2.0f * a0;
    if (lane < 8)
        g_U2[w * CC + 32 + lane] = g_HW[w * W2CAT + 32 + lane] + 2.0f * a1;
}

__global__ void k_final(const float* __restrict__ b2, float* __restrict__ out) {
    int w = (blockIdx.x * blockDim.x + threadIdx.x) >> 5;
    int lane = threadIdx.x & 31;
    if (w >= NN) return;
    int s = g_rowptr[w], e = g_rowptr[w + 1];
    float a0 = 0.f, a1 = 0.f;
    for (int t = s; t < e; t++) {
        int c = g_col[t];
        float wt = g_w[t];
        a0 += wt * g_U2[c * CC + lane];
        if (lane < 8) a1 += wt * g_U2[c * CC + 32 + lane];
    }
    float z0 = g_HW[w * W2CAT + 80 + lane] + a0 + b2[lane];
    float z1 = (lane < 8) ? (g_HW[w * W2CAT + 112 + lane] + a1 + b2[32 + lane])
                          : __int_as_float(0xff800000);
    float m = fmaxf(z0, z1);
    #pragma unroll
    for (int o = 16; o > 0; o >>= 1) m = fmaxf(m, __shfl_xor_sync(0xffffffffu, m, o));
    float ssum = expf(z0 - m) + ((lane < 8) ? expf(z1 - m) : 0.0f);
    #pragma unroll
    for (int o = 16; o > 0; o >>= 1) ssum += __shfl_xor_sync(0xffffffffu, ssum, o);
    float l = logf(ssum);
    out[w * CC + lane] = z0 - m - l;
    if (lane < 8) out[w * CC + 32 + lane] = z1 - m - l;
}

// ---------------- launch -----------------------------------------------------
extern "C" void kernel_launch(void* const* d_in, const int* in_sizes, int n_in,
                              void* d_out, int out_size) {
    // Resolve inputs BY ELEMENT COUNT (all six distinct):
    // x=5,000,000  ei=1,600,000  W1=19,200  b1=64  W2=7,680  b2=40
    const float* x  = nullptr;
    const void*  ei = nullptr;
    const float* W1 = nullptr;
    const float* b1 = nullptr;
    const float* W2 = nullptr;
    const float* b2 = nullptr;
    for (int i = 0; i < n_in; i++) {
        switch (in_sizes[i]) {
            case NN * FF:     x  = (const float*)d_in[i]; break;
            case 2 * EE:      ei = d_in[i];               break;
            case 3 * FF * HH: W1 = (const float*)d_in[i]; break;
            case HH:          b1 = (const float*)d_in[i]; break;
            case 3 * HH * CC: W2 = (const float*)d_in[i]; break;
            case CC:          b2 = (const float*)d_in[i]; break;
            default: break;
        }
    }
    const long long* ei64 = (const long long*)ei;
    const int*       ei32 = (const int*)ei;
    float* out = (float*)d_out;

    const int TB = 256;
    int nodeBlocks = (NN + TB - 1) / TB;
    int edgeBlocks = (EE + TB - 1) / TB;
    int warpRowBlocks = (NN * 32 + TB - 1) / TB;

    k_detect_dtype<<<1, 1024>>>(ei64);            // #1
    k_init<<<nodeBlocks, TB>>>(W1, W2);           // #2  zero deg + weight concat
    k_count_deg<<<edgeBlocks, TB>>>(ei64, ei32);  // #3
    k_scan1<<<SCAN_BLOCKS, 256>>>();              // #4
    k_scan2<<<1, 256>>>();                        // #5
    {   // #6 — profiled by ncu (-s 5 -c 1); depends only on k_init
        dim3 grid((NN + 63) / 64, (W1CAT + 63) / 64);
        k_gemm1<<<grid, 256>>>(x);
    }
    k_scan3<<<SCAN_BLOCKS, 256>>>();              // #7
    k_fill_csr<<<edgeBlocks, TB>>>(ei64, ei32);   // #8

    k_spmv_U<<<warpRowBlocks, TB>>>();
    k_spmv_h<<<warpRowBlocks, TB>>>(b1);

    {
        dim3 grid((NN + 63) / 64, (W2CAT + 63) / 64);
        k_gemm2<<<grid, 256>>>();
    }
    k_spmv_U2<<<warpRowBlocks, TB>>>();
    k_final<<<warpRowBlocks, TB>>>(b2, out);
}